// round 11
// baseline (speedup 1.0000x reference)
#include <cuda_runtime.h>
#include <cstdint>

#define BB   128          // batch
#define TT   1024         // time steps
#define INF  64           // input features
#define HH   256          // hidden (both layers)
#define OUTF 64           // output features
#define NCTA 128
#define NTHR 512
#define K0   (INF + HH)   // 320
#define K1   (2 * HH)     // 512

typedef unsigned long long ull;

// Persistent device state (static allocs allowed; no cudaMalloc anywhere)
__device__ __align__(16) float g_XT[TT * INF * BB];   // input transposed [t][i][b]
__device__ __align__(16) float g_h0[2 * HH * BB];     // layer0 h double-buffered [p][k][b]
__device__ __align__(16) float g_h1[2 * HH * BB];     // layer1 h double-buffered
__device__ __align__(16) float g_H1[TT * HH * BB];    // all layer1 h (deferred projection)
__device__ unsigned g_arrive = 0;                     // PROVEN ticket-barrier counters
__device__ unsigned g_release = 0;

__device__ __forceinline__ float sigf(float x) { return 1.0f / (1.0f + __expf(-x)); }

// PROVEN monotonic-ticket grid barrier (byte-exact semantics from the passing kernels).
__device__ __forceinline__ void grid_bar(unsigned rel_base, unsigned& barn)
{
    __syncthreads();
    if (threadIdx.x == 0) {
        __threadfence();
        barn++;
        unsigned prev = atomicAdd(&g_arrive, 1u);
        if (((prev + 1u) & (NCTA - 1u)) == 0u) {
            atomicAdd(&g_release, 1u);
        } else {
            unsigned need = rel_base + barn;
            while ((int)(*(volatile unsigned*)&g_release - need) < 0) { }
        }
        __threadfence();
    }
    __syncthreads();
}

// packed dual fp32 FMA: acc(lo,hi) += a(lo,hi) * b(lo,hi)
__device__ __forceinline__ void fma2(ull& acc, ull a, ull b)
{
    asm("fma.rn.f32x2 %0, %1, %2, %0;" : "+l"(acc) : "l"(a), "l"(b));
}
// splat float into both halves of a 64-bit pair (ALU pipe)
__device__ __forceinline__ ull pk(float x)
{
    ull r; asm("mov.b64 %0, {%1, %1};" : "=l"(r) : "f"(x)); return r;
}

// GMEM-fed GEMM (proven round-9 path, byte-identical): row-paired FFMA2,
// 1-group LDG prefetch pipeline. Used for x and h1 segments only.
__device__ __forceinline__ void gemm_seg(ull* acc,
                                         const ulonglong2* __restrict__ ws,
                                         int ks, int ke,
                                         const float* __restrict__ act, int koff, int lane)
{
    const char* ap = (const char*)act + (size_t)(ks - koff) * (BB * 4) + lane * 16;
    const char* pe = (const char*)act + (size_t)(ke - koff) * (BB * 4) + lane * 16;
    float4 buf[4];
#pragma unroll
    for (int j = 0; j < 4; j++)
        buf[j] = __ldcg(reinterpret_cast<const float4*>(ap + j * (BB * 4)));
    const char* pf = ap + 4 * (BB * 4);
    const ulonglong2* wp = ws + (size_t)ks * 2;

    for (int k = ks; k < ke; k += 4) {
#pragma unroll
        for (int j = 0; j < 4; j++) {
            const float4 a = buf[j];
            if (pf < pe) buf[j] = __ldcg(reinterpret_cast<const float4*>(pf));
            pf += BB * 4;
            const ull s0 = pk(a.x), s1 = pk(a.y), s2 = pk(a.z), s3 = pk(a.w);
            const ulonglong2 wlo = wp[0];
            const ulonglong2 whi = wp[1];
            wp += 2;
            fma2(acc[0],  wlo.x, s0); fma2(acc[1],  wlo.x, s1);
            fma2(acc[2],  wlo.x, s2); fma2(acc[3],  wlo.x, s3);
            fma2(acc[4],  wlo.y, s0); fma2(acc[5],  wlo.y, s1);
            fma2(acc[6],  wlo.y, s2); fma2(acc[7],  wlo.y, s3);
            fma2(acc[8],  whi.x, s0); fma2(acc[9],  whi.x, s1);
            fma2(acc[10], whi.x, s2); fma2(acc[11], whi.x, s3);
            fma2(acc[12], whi.y, s0); fma2(acc[13], whi.y, s1);
            fma2(acc[14], whi.y, s2); fma2(acc[15], whi.y, s3);
        }
    }
}

// SMEM-fed GEMM (round-10): activations staged in SMEM by cp.async; LDS lat 29
// is hidden by unrolling — no prefetch machinery, no L2 exposure.
__device__ __forceinline__ void gemm_smem(ull* acc,
                                          const ulonglong2* __restrict__ ws,
                                          int ks, int ke,
                                          const float* __restrict__ actsm, int koff, int lane)
{
    const float4* ap = reinterpret_cast<const float4*>(actsm + (size_t)(ks - koff) * BB) + lane;
    const ulonglong2* wp = ws + (size_t)ks * 2;
#pragma unroll 4
    for (int k = ks; k < ke; k++) {
        const float4 a = *ap; ap += BB / 4;
        const ull s0 = pk(a.x), s1 = pk(a.y), s2 = pk(a.z), s3 = pk(a.w);
        const ulonglong2 wlo = wp[0];
        const ulonglong2 whi = wp[1];
        wp += 2;
        fma2(acc[0],  wlo.x, s0); fma2(acc[1],  wlo.x, s1);
        fma2(acc[2],  wlo.x, s2); fma2(acc[3],  wlo.x, s3);
        fma2(acc[4],  wlo.y, s0); fma2(acc[5],  wlo.y, s1);
        fma2(acc[6],  wlo.y, s2); fma2(acc[7],  wlo.y, s3);
        fma2(acc[8],  whi.x, s0); fma2(acc[9],  whi.x, s1);
        fma2(acc[10], whi.x, s2); fma2(acc[11], whi.x, s3);
        fma2(acc[12], whi.y, s0); fma2(acc[13], whi.y, s1);
        fma2(acc[14], whi.y, s2); fma2(acc[15], whi.y, s3);
    }
}

// SMEM layout (floats):
#define OFS_WS0 0                      // [K0][8]   layer0 weights
#define OFS_WS1 2560                   // [K1][8]   layer1 weights
#define OFS_ACT 6656                   // [256][128] staged h0(tau-1)  (131KB)
#define OFS_P0  39424                  // [8 kq][4 g][128 c][2 u] layer0 partials
#define OFS_P1  47616                  // layer1 partials
#define OFS_CST 55808                  // [2 l][2 u][128 c] cell state
#define OFS_BIA 56320                  // [2 l][8 r] biases
#define SM_FLOATS 56336                // 225,344 B  (limit 232,448)
#define SM_BYTES  (SM_FLOATS * 4)

extern "C" __global__ void __launch_bounds__(NTHR, 1)
lstm_persistent_kernel(const float* __restrict__ input,
                       const float* __restrict__ W_ih0, const float* __restrict__ W_hh0,
                       const float* __restrict__ b_ih0, const float* __restrict__ b_hh0,
                       const float* __restrict__ W_ih1, const float* __restrict__ W_hh1,
                       const float* __restrict__ b_ih1, const float* __restrict__ b_hh1,
                       const float* __restrict__ W_lin, const float* __restrict__ b_lin,
                       float* __restrict__ out)
{
    extern __shared__ float sm[];
    const int cta  = blockIdx.x;
    const int tid  = threadIdx.x;
    const int w    = tid >> 5;
    const int lane = tid & 31;

    unsigned rel_base = *(volatile unsigned*)&g_release;   // quiescent at launch start
    unsigned barn = 0;

    // ---- Phase 0: init state, stage weights, transpose input ----
    for (int i = tid; i < 512; i += NTHR) sm[OFS_CST + i] = 0.f;
    for (int i = cta * NTHR + tid; i < 2 * HH * BB; i += NCTA * NTHR) {
        g_h0[i] = 0.f;
        g_h1[i] = 0.f;
    }
    for (int i = tid; i < K0 * 8; i += NTHR) {
        int k = i >> 3, r = i & 7;
        int row = (r >> 1) * HH + 2 * cta + (r & 1);
        sm[OFS_WS0 + i] = (k < INF) ? W_ih0[row * INF + k] : W_hh0[row * HH + (k - INF)];
    }
    for (int i = tid; i < K1 * 8; i += NTHR) {
        int k = i >> 3, r = i & 7;
        int row = (r >> 1) * HH + 2 * cta + (r & 1);
        sm[OFS_WS1 + i] = (k < HH) ? W_ih1[row * HH + k] : W_hh1[row * HH + (k - HH)];
    }
    if (tid < 16) {
        int l = tid >> 3, r = tid & 7;
        int row = (r >> 1) * HH + 2 * cta + (r & 1);
        sm[OFS_BIA + tid] = l ? (b_ih1[row] + b_hh1[row]) : (b_ih0[row] + b_hh0[row]);
    }
    for (int t = cta * 8; t < cta * 8 + 8; t++) {
        for (int i = tid; i < INF * BB; i += NTHR) {
            int ii = i >> 7, b = i & 127;
            g_XT[t * INF * BB + ii * BB + b] = input[(size_t)b * TT * INF + t * INF + ii];
        }
    }
    grid_bar(rel_base, barn);

    const ulonglong2* ws = reinterpret_cast<const ulonglong2*>(sm + ((w < 8) ? OFS_WS0 : OFS_WS1));
    float* pbase = sm + ((w < 8) ? OFS_P0 : OFS_P1) + (w & 7) * 1024;
    const uint32_t act_saddr = (uint32_t)__cvta_generic_to_shared(sm + OFS_ACT);

    // ew role (all 512 threads, 1 scalar item each): layer el, unit eu, col ec
    const int el = tid >> 8;
    const int eu = (tid >> 7) & 1;
    const int ec = tid & 127;

    // ---- Main loop: tick tau = layer0(tau) + layer1(tau-1); one barrier/tick ----
    for (int tau = 0; tau <= TT; tau++) {
        const int pw = tau & 1;
        const int pr = pw ^ 1;

        // Stage h0(tau-1) [256][128] fp32 into SMEM via cp.async (all threads).
        {
            const char* src = (const char*)(g_h0 + pr * HH * BB) + tid * 16;
            uint32_t dst = act_saddr + tid * 16;
#pragma unroll
            for (int i = 0; i < 16; i++) {
                asm volatile("cp.async.cg.shared.global [%0], [%1], 16;"
                             :: "r"(dst), "l"(src));
                dst += NTHR * 16; src += NTHR * 16;
            }
            asm volatile("cp.async.commit_group;" ::: "memory");
        }

        ull acc[16];
#pragma unroll
        for (int r = 0; r < 16; r++) acc[r] = 0ull;
        bool did = false;

        // Phase A (overlaps the cp.async fill): GMEM-fed segments — x and h1.
        if (w == 0) {
            if (tau < TT) { did = true;
                gemm_seg(acc, ws, 0, 40, g_XT + tau * INF * BB, 0, lane); }
        } else if (w == 1) {
            if (tau < TT) { did = true;
                gemm_seg(acc, ws, 40, 64, g_XT + tau * INF * BB, 0, lane); }
        } else if (w >= 12) {
            if (tau >= 1) { did = true;
                gemm_seg(acc, ws, (w - 8) * 64, (w - 8) * 64 + 64,
                         g_h1 + pw * HH * BB, HH, lane); }
        }

        asm volatile("cp.async.wait_group 0;" ::: "memory");
        __syncthreads();

        // Phase B: SMEM-fed h0 segments.
        if (w < 8) {
            if (tau < TT) {
                const int ke = w * 40 + 40;
                const int ks = (w * 40 < INF) ? INF : w * 40;
                if (ke > ks) { did = true;
                    gemm_smem(acc, ws, ks, ke, sm + OFS_ACT, INF, lane); }
            }
        } else if (w < 12) {
            if (tau >= 1) { did = true;
                gemm_smem(acc, ws, (w - 8) * 64, (w - 8) * 64 + 64,
                          sm + OFS_ACT, 0, lane); }
        }

        if (did) {
            ull* pp = reinterpret_cast<ull*>(pbase);
#pragma unroll
            for (int rp = 0; rp < 4; rp++) {
                ulonglong2 v01; v01.x = acc[rp * 4 + 0]; v01.y = acc[rp * 4 + 1];
                ulonglong2 v23; v23.x = acc[rp * 4 + 2]; v23.y = acc[rp * 4 + 3];
                *reinterpret_cast<ulonglong2*>(pp + rp * 128 + 4 * lane)     = v01;
                *reinterpret_cast<ulonglong2*>(pp + rp * 128 + 4 * lane + 2) = v23;
            }
        }
        __syncthreads();

        // elementwise: each thread owns ONE (layer, unit, col) scalar
        {
            const bool doit = (el == 0) ? (tau < TT) : (tau >= 1);
            if (doit) {
                const float* pb = sm + (el ? OFS_P1 : OFS_P0);
                float gv[4];
#pragma unroll
                for (int g = 0; g < 4; g++) {
                    const int roff = g * 256 + ec * 2 + eu;   // [g][c][u]
                    float s = pb[roff];
#pragma unroll
                    for (int q = 1; q < 8; q++) s += pb[q * 1024 + roff];
                    gv[g] = s + sm[OFS_BIA + el * 8 + g * 2 + eu];
                }
                const int coff = OFS_CST + (el * 2 + eu) * 128 + ec;
                const float c_old = sm[coff];
                const float cn = sigf(gv[1]) * c_old + sigf(gv[0]) * tanhf(gv[2]);
                sm[coff] = cn;
                const float hn = sigf(gv[3]) * tanhf(cn);
                const int row = 2 * cta + eu;
                if (el == 0) {
                    __stcg(&g_h0[pw * HH * BB + row * BB + ec], hn);
                } else {
                    __stcg(&g_h1[pr * HH * BB + row * BB + ec], hn);
                    __stcg(&g_H1[(size_t)(tau - 1) * HH * BB + row * BB + ec], hn);
                }
            }
        }
        grid_bar(rel_base, barn);
    }

    // ---- Deferred projection: out[b][t][o] = h1(t) . W_lin[o] + b_lin[o] ----
    for (int i = tid; i < OUTF * HH; i += NTHR) sm[i] = W_lin[i];
    if (tid < OUTF) sm[OUTF * HH + tid] = b_lin[tid];
    __syncthreads();

    const int t = cta * 8 + (w & 7);
    const int obase = (w >> 3) * 32;
    const int bb4 = lane * 4;
    const float* hb = g_H1 + (size_t)t * HH * BB;
    for (int ob = obase; ob < obase + 32; ob += 8) {
        float acc[8][4];
#pragma unroll
        for (int oo = 0; oo < 8; oo++) { acc[oo][0] = acc[oo][1] = acc[oo][2] = acc[oo][3] = 0.f; }
        for (int j = 0; j < HH; j++) {
            const float4 hv = *reinterpret_cast<const float4*>(hb + j * BB + bb4);
#pragma unroll
            for (int oo = 0; oo < 8; oo++) {
                const float wv = sm[(ob + oo) * HH + j];
                acc[oo][0] += wv * hv.x; acc[oo][1] += wv * hv.y;
                acc[oo][2] += wv * hv.z; acc[oo][3] += wv * hv.w;
            }
        }
#pragma unroll
        for (int oo = 0; oo < 8; oo++) {
            const int o = ob + oo;
            const float bl = sm[OUTF * HH + o];
            out[(size_t)(bb4 + 0) * TT * OUTF + t * OUTF + o] = acc[oo][0] + bl;
            out[(size_t)(bb4 + 1) * TT * OUTF + t * OUTF + o] = acc[oo][1] + bl;
            out[(size_t)(bb4 + 2) * TT * OUTF + t * OUTF + o] = acc[oo][2] + bl;
            out[(size_t)(bb4 + 3) * TT * OUTF + t * OUTF + o] = acc[oo][3] + bl;
        }
    }
}

extern "C" void kernel_launch(void* const* d_in, const int* in_sizes, int n_in,
                              void* d_out, int out_size)
{
    (void)in_sizes; (void)n_in; (void)out_size;
    cudaFuncSetAttribute(lstm_persistent_kernel,
                         cudaFuncAttributeMaxDynamicSharedMemorySize, SM_BYTES);
    lstm_persistent_kernel<<<NCTA, NTHR, SM_BYTES>>>(
        (const float*)d_in[0],
        (const float*)d_in[1], (const float*)d_in[2],
        (const float*)d_in[3], (const float*)d_in[4],
        (const float*)d_in[5], (const float*)d_in[6],
        (const float*)d_in[7], (const float*)d_in[8],
        (const float*)d_in[9], (const float*)d_in[10],
        (float*)d_out);
}

// round 12
// speedup vs baseline: 1.2119x; 1.2119x over previous
#include <cuda_runtime.h>
#include <cstdint>

#define BB   128          // batch
#define TT   1024         // time steps
#define INF  64           // input features
#define HH   256          // hidden (both layers)
#define OUTF 64           // output features
#define NCTA 128
#define NTHR 512
#define K0   (INF + HH)   // 320
#define K1   (2 * HH)     // 512

typedef unsigned long long ull;

// Persistent device state (static allocs allowed; no cudaMalloc anywhere)
__device__ __align__(16) float g_XT[TT * INF * BB];   // input transposed [t][i][b]
__device__ __align__(16) float g_h0[2 * HH * BB];     // layer0 h double-buffered [p][k][b]
__device__ __align__(16) float g_h1[2 * HH * BB];     // layer1 h double-buffered
__device__ __align__(16) float g_H1[TT * HH * BB];    // all layer1 h (deferred projection)
__device__ unsigned g_arrive = 0;                     // PROVEN ticket-barrier counters
__device__ unsigned g_release = 0;

__device__ __forceinline__ float sigf(float x) { return 1.0f / (1.0f + __expf(-x)); }

// PROVEN monotonic-ticket grid barrier (byte-exact semantics from the passing kernels).
__device__ __forceinline__ void grid_bar(unsigned rel_base, unsigned& barn)
{
    __syncthreads();
    if (threadIdx.x == 0) {
        __threadfence();
        barn++;
        unsigned prev = atomicAdd(&g_arrive, 1u);
        if (((prev + 1u) & (NCTA - 1u)) == 0u) {
            atomicAdd(&g_release, 1u);
        } else {
            unsigned need = rel_base + barn;
            while ((int)(*(volatile unsigned*)&g_release - need) < 0) { }
        }
        __threadfence();
    }
    __syncthreads();
}

// packed dual fp32 FMA: acc(lo,hi) += a(lo,hi) * b(lo,hi)
__device__ __forceinline__ void fma2(ull& acc, ull a, ull b)
{
    asm("fma.rn.f32x2 %0, %1, %2, %0;" : "+l"(acc) : "l"(a), "l"(b));
}
// splat float into both halves of a 64-bit pair (ALU pipe)
__device__ __forceinline__ ull pk(float x)
{
    ull r; asm("mov.b64 %0, {%1, %1};" : "=l"(r) : "f"(x)); return r;
}

// GMEM-fed GEMM (proven round-9 path, byte-identical): row-paired FFMA2,
// 1-group LDG prefetch pipeline.
__device__ __forceinline__ void gemm_seg(ull* acc,
                                         const ulonglong2* __restrict__ ws,
                                         int ks, int ke,
                                         const float* __restrict__ act, int koff, int lane)
{
    const char* ap = (const char*)act + (size_t)(ks - koff) * (BB * 4) + lane * 16;
    const char* pe = (const char*)act + (size_t)(ke - koff) * (BB * 4) + lane * 16;
    float4 buf[4];
#pragma unroll
    for (int j = 0; j < 4; j++)
        buf[j] = __ldcg(reinterpret_cast<const float4*>(ap + j * (BB * 4)));
    const char* pf = ap + 4 * (BB * 4);
    const ulonglong2* wp = ws + (size_t)ks * 2;

    for (int k = ks; k < ke; k += 4) {
#pragma unroll
        for (int j = 0; j < 4; j++) {
            const float4 a = buf[j];
            if (pf < pe) buf[j] = __ldcg(reinterpret_cast<const float4*>(pf));
            pf += BB * 4;
            const ull s0 = pk(a.x), s1 = pk(a.y), s2 = pk(a.z), s3 = pk(a.w);
            const ulonglong2 wlo = wp[0];        // row-pairs (r0,r1), (r2,r3)
            const ulonglong2 whi = wp[1];        // row-pairs (r4,r5), (r6,r7)
            wp += 2;
            fma2(acc[0],  wlo.x, s0); fma2(acc[1],  wlo.x, s1);
            fma2(acc[2],  wlo.x, s2); fma2(acc[3],  wlo.x, s3);
            fma2(acc[4],  wlo.y, s0); fma2(acc[5],  wlo.y, s1);
            fma2(acc[6],  wlo.y, s2); fma2(acc[7],  wlo.y, s3);
            fma2(acc[8],  whi.x, s0); fma2(acc[9],  whi.x, s1);
            fma2(acc[10], whi.x, s2); fma2(acc[11], whi.x, s3);
            fma2(acc[12], whi.y, s0); fma2(acc[13], whi.y, s1);
            fma2(acc[14], whi.y, s2); fma2(acc[15], whi.y, s3);
        }
    }
}

// Round-12 balanced k-split (all segment pieces %4):
//   L0 (warps 0..5):  [56,56,52,52,52,52] over K0=320
//   L1 (warps 6..15): [52x8, 48, 48]      over K1=512
__device__ __forceinline__ int l0_start(int w) { return w * 52 + min(w, 2) * 4; }
__device__ __forceinline__ int l0_len(int w)   { return (w < 2) ? 56 : 52; }
__device__ __forceinline__ int l1_start(int i) { return min(i, 8) * 52 + max(i - 8, 0) * 48; }
__device__ __forceinline__ int l1_len(int i)   { return (i < 8) ? 52 : 48; }

// SMEM layout (floats):
#define OFS_WS0 0                      // [K0][8]   layer0 weights (rows = gate*2+unit)
#define OFS_WS1 2560                   // [K1][8]   layer1 weights
#define OFS_P0  6656                   // [6 slot][4 g][128 c][2 u] layer0 partials
#define OFS_P1  12800                  // [10 slot][4 g][128 c][2 u] layer1 partials
#define OFS_CST 23040                  // [2 l][2 u][128 c] cell state
#define OFS_BIA 23552                  // [2 l][8 r] biases
#define SM_FLOATS 23568                // >= 16448 needed by projection phase
#define SM_BYTES  (SM_FLOATS * 4)

extern "C" __global__ void __launch_bounds__(NTHR, 1)
lstm_persistent_kernel(const float* __restrict__ input,
                       const float* __restrict__ W_ih0, const float* __restrict__ W_hh0,
                       const float* __restrict__ b_ih0, const float* __restrict__ b_hh0,
                       const float* __restrict__ W_ih1, const float* __restrict__ W_hh1,
                       const float* __restrict__ b_ih1, const float* __restrict__ b_hh1,
                       const float* __restrict__ W_lin, const float* __restrict__ b_lin,
                       float* __restrict__ out)
{
    extern __shared__ float sm[];
    const int cta  = blockIdx.x;
    const int tid  = threadIdx.x;
    const int w    = tid >> 5;         // 0..5 layer0 k-slices, 6..15 layer1 k-slices
    const int lane = tid & 31;

    unsigned rel_base = *(volatile unsigned*)&g_release;   // quiescent at launch start
    unsigned barn = 0;

    // ---- Phase 0: init state, stage weights, transpose input ----
    for (int i = tid; i < 512; i += NTHR) sm[OFS_CST + i] = 0.f;
    for (int i = cta * NTHR + tid; i < 2 * HH * BB; i += NCTA * NTHR) {
        g_h0[i] = 0.f;
        g_h1[i] = 0.f;
    }
    // ws0[k*8 + r] = W0[(r>>1)*HH + 2*cta + (r&1)][k], k<INF from W_ih0 else W_hh0
    for (int i = tid; i < K0 * 8; i += NTHR) {
        int k = i >> 3, r = i & 7;
        int row = (r >> 1) * HH + 2 * cta + (r & 1);
        sm[OFS_WS0 + i] = (k < INF) ? W_ih0[row * INF + k] : W_hh0[row * HH + (k - INF)];
    }
    for (int i = tid; i < K1 * 8; i += NTHR) {
        int k = i >> 3, r = i & 7;
        int row = (r >> 1) * HH + 2 * cta + (r & 1);
        sm[OFS_WS1 + i] = (k < HH) ? W_ih1[row * HH + k] : W_hh1[row * HH + (k - HH)];
    }
    if (tid < 16) {
        int l = tid >> 3, r = tid & 7;
        int row = (r >> 1) * HH + 2 * cta + (r & 1);
        sm[OFS_BIA + tid] = l ? (b_ih1[row] + b_hh1[row]) : (b_ih0[row] + b_hh0[row]);
    }
    // transpose this CTA's 8 timesteps: XT[t][i][b] = input[b][t][i]
    for (int t = cta * 8; t < cta * 8 + 8; t++) {
        for (int i = tid; i < INF * BB; i += NTHR) {
            int ii = i >> 7, b = i & 127;
            g_XT[t * INF * BB + ii * BB + b] = input[(size_t)b * TT * INF + t * INF + ii];
        }
    }
    grid_bar(rel_base, barn);

    const ulonglong2* ws = reinterpret_cast<const ulonglong2*>(sm + ((w < 6) ? OFS_WS0 : OFS_WS1));
    float* pbase = sm + ((w < 6) ? (OFS_P0 + w * 1024) : (OFS_P1 + (w - 6) * 1024));

    // ew role (all 512 threads, 1 scalar item each): layer el, unit eu, col ec
    const int el = tid >> 8;
    const int eu = (tid >> 7) & 1;
    const int ec = tid & 127;

    // ---- Main loop: tick tau = layer0(tau) + layer1(tau-1); one barrier/tick ----
    for (int tau = 0; tau <= TT; tau++) {
        const int pw = tau & 1;
        const int pr = pw ^ 1;

        ull acc[16];
#pragma unroll
        for (int r = 0; r < 16; r++) acc[r] = 0ull;

        bool did = false;
        if (w < 6) {
            if (tau < TT) {
                did = true;
                const int ks = l0_start(w), ke = ks + l0_len(w);
                if (ks < INF)   // x segment
                    gemm_seg(acc, ws, ks, min(ke, INF),
                             g_XT + tau * INF * BB, 0, lane);
                if (ke > INF)   // h0(tau-1) segment
                    gemm_seg(acc, ws, max(ks, INF), ke,
                             g_h0 + pr * HH * BB, INF, lane);
            }
        } else {
            if (tau >= 1) {
                did = true;
                const int idx = w - 6;
                const int ks = l1_start(idx), ke = ks + l1_len(idx);
                if (ks < HH)    // h0(tau-1) segment
                    gemm_seg(acc, ws, ks, min(ke, HH),
                             g_h0 + pr * HH * BB, 0, lane);
                if (ke > HH)    // h1(tau-2) segment
                    gemm_seg(acc, ws, max(ks, HH), ke,
                             g_h1 + pw * HH * BB, HH, lane);
            }
        }
        if (did) {
            // partial layout per warp slot: ull pp[4 g][128 c], pp[g][c] = (unit0, unit1)
            ull* pp = reinterpret_cast<ull*>(pbase);
#pragma unroll
            for (int rp = 0; rp < 4; rp++) {
                ulonglong2 v01; v01.x = acc[rp * 4 + 0]; v01.y = acc[rp * 4 + 1];
                ulonglong2 v23; v23.x = acc[rp * 4 + 2]; v23.y = acc[rp * 4 + 3];
                *reinterpret_cast<ulonglong2*>(pp + rp * 128 + 4 * lane)     = v01;
                *reinterpret_cast<ulonglong2*>(pp + rp * 128 + 4 * lane + 2) = v23;
            }
        }
        __syncthreads();

        // elementwise: each thread owns ONE (layer, unit, col) scalar
        {
            const bool doit = (el == 0) ? (tau < TT) : (tau >= 1);
            if (doit) {
                const float* pb = sm + (el ? OFS_P1 : OFS_P0);
                const int nq = el ? 10 : 6;
                float gv[4];
#pragma unroll
                for (int g = 0; g < 4; g++) {
                    const int roff = g * 256 + ec * 2 + eu;   // [g][c][u]
                    float s = pb[roff];
                    for (int q = 1; q < nq; q++) s += pb[q * 1024 + roff];
                    gv[g] = s + sm[OFS_BIA + el * 8 + g * 2 + eu];
                }
                const int coff = OFS_CST + (el * 2 + eu) * 128 + ec;
                const float c_old = sm[coff];
                const float cn = sigf(gv[1]) * c_old + sigf(gv[0]) * tanhf(gv[2]);
                sm[coff] = cn;
                const float hn = sigf(gv[3]) * tanhf(cn);
                const int row = 2 * cta + eu;
                if (el == 0) {
                    __stcg(&g_h0[pw * HH * BB + row * BB + ec], hn);
                } else {
                    __stcg(&g_h1[pr * HH * BB + row * BB + ec], hn);
                    __stcg(&g_H1[(size_t)(tau - 1) * HH * BB + row * BB + ec], hn);
                }
            }
        }
        grid_bar(rel_base, barn);
    }

    // ---- Deferred projection: out[b][t][o] = h1(t) . W_lin[o] + b_lin[o] ----
    for (int i = tid; i < OUTF * HH; i += NTHR) sm[i] = W_lin[i];
    if (tid < OUTF) sm[OUTF * HH + tid] = b_lin[tid];
    __syncthreads();

    // 16 warps: warp w handles timestep cta*8 + (w&7), output block (w>>3)*32..+32
    const int t = cta * 8 + (w & 7);
    const int obase = (w >> 3) * 32;
    const int bb4 = lane * 4;
    const float* hb = g_H1 + (size_t)t * HH * BB;
    for (int ob = obase; ob < obase + 32; ob += 8) {
        float acc[8][4];
#pragma unroll
        for (int oo = 0; oo < 8; oo++) { acc[oo][0] = acc[oo][1] = acc[oo][2] = acc[oo][3] = 0.f; }
        for (int j = 0; j < HH; j++) {
            const float4 hv = *reinterpret_cast<const float4*>(hb + j * BB + bb4);
#pragma unroll
            for (int oo = 0; oo < 8; oo++) {
                const float wv = sm[(ob + oo) * HH + j];
                acc[oo][0] += wv * hv.x; acc[oo][1] += wv * hv.y;
                acc[oo][2] += wv * hv.z; acc[oo][3] += wv * hv.w;
            }
        }
#pragma unroll
        for (int oo = 0; oo < 8; oo++) {
            const int o = ob + oo;
            const float bl = sm[OUTF * HH + o];
            out[(size_t)(bb4 + 0) * TT * OUTF + t * OUTF + o] = acc[oo][0] + bl;
            out[(size_t)(bb4 + 1) * TT * OUTF + t * OUTF + o] = acc[oo][1] + bl;
            out[(size_t)(bb4 + 2) * TT * OUTF + t * OUTF + o] = acc[oo][2] + bl;
            out[(size_t)(bb4 + 3) * TT * OUTF + t * OUTF + o] = acc[oo][3] + bl;
        }
    }
}

extern "C" void kernel_launch(void* const* d_in, const int* in_sizes, int n_in,
                              void* d_out, int out_size)
{
    (void)in_sizes; (void)n_in; (void)out_size;
    cudaFuncSetAttribute(lstm_persistent_kernel,
                         cudaFuncAttributeMaxDynamicSharedMemorySize, SM_BYTES);
    lstm_persistent_kernel<<<NCTA, NTHR, SM_BYTES>>>(
        (const float*)d_in[0],
        (const float*)d_in[1], (const float*)d_in[2],
        (const float*)d_in[3], (const float*)d_in[4],
        (const float*)d_in[5], (const float*)d_in[6],
        (const float*)d_in[7], (const float*)d_in[8],
        (const float*)d_in[9], (const float*)d_in[10],
        (float*)d_out);
}

// round 13
// speedup vs baseline: 1.2201x; 1.0068x over previous
#include <cuda_runtime.h>
#include <cstdint>

#define BB   128          // batch
#define TT   1024         // time steps
#define INF  64           // input features
#define HH   256          // hidden (both layers)
#define OUTF 64           // output features
#define NCTA 128
#define NTHR 512
#define K0   (INF + HH)   // 320
#define K1   (2 * HH)     // 512

typedef unsigned long long ull;

// Persistent device state (static allocs allowed; no cudaMalloc anywhere)
__device__ __align__(16) float g_XT[TT * INF * BB];   // input transposed [t][i][b]
__device__ __align__(16) float g_h0[2 * HH * BB];     // layer0 h double-buffered [p][k][b]
__device__ __align__(16) float g_h1[2 * HH * BB];     // layer1 h double-buffered
__device__ __align__(16) float g_H1[TT * HH * BB];    // all layer1 h (deferred projection)
// Round-13 hierarchical barrier state: 8 group counters (256B apart -> distinct
// LTS slices so the 16-arrivals-per-group drain in parallel), one top counter,
// one release word. All monotonic (graph-replay safe, same as proven ticket).
__device__ unsigned g_grp[8 * 64];
__device__ unsigned g_top = 0;
__device__ unsigned g_release = 0;

__device__ __forceinline__ float sigf(float x) { return 1.0f / (1.0f + __expf(-x)); }

// Hierarchical monotonic-ticket grid barrier. Arrival: cta -> group(16) -> top(8)
// -> release. Poll structure is byte-identical to the proven flat version.
__device__ __forceinline__ void grid_bar(unsigned rel_base, unsigned& barn, int grp)
{
    __syncthreads();
    if (threadIdx.x == 0) {
        __threadfence();
        barn++;
        bool releaser = false;
        unsigned p = atomicAdd(&g_grp[grp * 64], 1u);
        if (((p + 1u) & 15u) == 0u) {                 // last of 16 in group this tick
            unsigned q = atomicAdd(&g_top, 1u);
            if (((q + 1u) & 7u) == 0u) {              // last group this tick
                atomicAdd(&g_release, 1u);
                releaser = true;
            }
        }
        if (!releaser) {
            unsigned need = rel_base + barn;
            while ((int)(*(volatile unsigned*)&g_release - need) < 0) { }
        }
        __threadfence();
    }
    __syncthreads();
}

// packed dual fp32 FMA: acc(lo,hi) += a(lo,hi) * b(lo,hi)
__device__ __forceinline__ void fma2(ull& acc, ull a, ull b)
{
    asm("fma.rn.f32x2 %0, %1, %2, %0;" : "+l"(acc) : "l"(a), "l"(b));
}
// splat float into both halves of a 64-bit pair (ALU pipe)
__device__ __forceinline__ ull pk(float x)
{
    ull r; asm("mov.b64 %0, {%1, %1};" : "=l"(r) : "f"(x)); return r;
}

// GMEM-fed GEMM (proven round-9 path, byte-identical): row-paired FFMA2,
// 1-group LDG prefetch pipeline.
__device__ __forceinline__ void gemm_seg(ull* acc,
                                         const ulonglong2* __restrict__ ws,
                                         int ks, int ke,
                                         const float* __restrict__ act, int koff, int lane)
{
    const char* ap = (const char*)act + (size_t)(ks - koff) * (BB * 4) + lane * 16;
    const char* pe = (const char*)act + (size_t)(ke - koff) * (BB * 4) + lane * 16;
    float4 buf[4];
#pragma unroll
    for (int j = 0; j < 4; j++)
        buf[j] = __ldcg(reinterpret_cast<const float4*>(ap + j * (BB * 4)));
    const char* pf = ap + 4 * (BB * 4);
    const ulonglong2* wp = ws + (size_t)ks * 2;

    for (int k = ks; k < ke; k += 4) {
#pragma unroll
        for (int j = 0; j < 4; j++) {
            const float4 a = buf[j];
            if (pf < pe) buf[j] = __ldcg(reinterpret_cast<const float4*>(pf));
            pf += BB * 4;
            const ull s0 = pk(a.x), s1 = pk(a.y), s2 = pk(a.z), s3 = pk(a.w);
            const ulonglong2 wlo = wp[0];        // row-pairs (r0,r1), (r2,r3)
            const ulonglong2 whi = wp[1];        // row-pairs (r4,r5), (r6,r7)
            wp += 2;
            fma2(acc[0],  wlo.x, s0); fma2(acc[1],  wlo.x, s1);
            fma2(acc[2],  wlo.x, s2); fma2(acc[3],  wlo.x, s3);
            fma2(acc[4],  wlo.y, s0); fma2(acc[5],  wlo.y, s1);
            fma2(acc[6],  wlo.y, s2); fma2(acc[7],  wlo.y, s3);
            fma2(acc[8],  whi.x, s0); fma2(acc[9],  whi.x, s1);
            fma2(acc[10], whi.x, s2); fma2(acc[11], whi.x, s3);
            fma2(acc[12], whi.y, s0); fma2(acc[13], whi.y, s1);
            fma2(acc[14], whi.y, s2); fma2(acc[15], whi.y, s3);
        }
    }
}

// SMEM layout (floats):
#define OFS_WS0 0                      // [K0][8]   layer0 weights (rows = gate*2+unit)
#define OFS_WS1 2560                   // [K1][8]   layer1 weights
#define OFS_P0  6656                   // [8 kq][4 g][128 c][2 u] layer0 partials
#define OFS_P1  14848                  // [8 kq][4 g][128 c][2 u] layer1 partials
#define OFS_CST 23040                  // [2 l][2 u][128 c] cell state
#define OFS_BIA 23552                  // [2 l][8 r] biases
#define SM_FLOATS 23568                // >= 16448 needed by projection phase
#define SM_BYTES  (SM_FLOATS * 4)

extern "C" __global__ void __launch_bounds__(NTHR, 1)
lstm_persistent_kernel(const float* __restrict__ input,
                       const float* __restrict__ W_ih0, const float* __restrict__ W_hh0,
                       const float* __restrict__ b_ih0, const float* __restrict__ b_hh0,
                       const float* __restrict__ W_ih1, const float* __restrict__ W_hh1,
                       const float* __restrict__ b_ih1, const float* __restrict__ b_hh1,
                       const float* __restrict__ W_lin, const float* __restrict__ b_lin,
                       float* __restrict__ out)
{
    extern __shared__ float sm[];
    const int cta  = blockIdx.x;
    const int tid  = threadIdx.x;
    const int w    = tid >> 5;         // 0..7 layer0 k-eighths, 8..15 layer1 k-eighths
    const int lane = tid & 31;
    const int grp  = cta & 7;          // barrier arrival group

    unsigned rel_base = *(volatile unsigned*)&g_release;   // quiescent at launch start
    unsigned barn = 0;

    // ---- Phase 0: init state, stage weights, transpose input ----
    for (int i = tid; i < 512; i += NTHR) sm[OFS_CST + i] = 0.f;
    for (int i = cta * NTHR + tid; i < 2 * HH * BB; i += NCTA * NTHR) {
        g_h0[i] = 0.f;
        g_h1[i] = 0.f;
    }
    // ws0[k*8 + r] = W0[(r>>1)*HH + 2*cta + (r&1)][k], k<INF from W_ih0 else W_hh0
    for (int i = tid; i < K0 * 8; i += NTHR) {
        int k = i >> 3, r = i & 7;
        int row = (r >> 1) * HH + 2 * cta + (r & 1);
        sm[OFS_WS0 + i] = (k < INF) ? W_ih0[row * INF + k] : W_hh0[row * HH + (k - INF)];
    }
    for (int i = tid; i < K1 * 8; i += NTHR) {
        int k = i >> 3, r = i & 7;
        int row = (r >> 1) * HH + 2 * cta + (r & 1);
        sm[OFS_WS1 + i] = (k < HH) ? W_ih1[row * HH + k] : W_hh1[row * HH + (k - HH)];
    }
    if (tid < 16) {
        int l = tid >> 3, r = tid & 7;
        int row = (r >> 1) * HH + 2 * cta + (r & 1);
        sm[OFS_BIA + tid] = l ? (b_ih1[row] + b_hh1[row]) : (b_ih0[row] + b_hh0[row]);
    }
    // transpose this CTA's 8 timesteps: XT[t][i][b] = input[b][t][i]
    for (int t = cta * 8; t < cta * 8 + 8; t++) {
        for (int i = tid; i < INF * BB; i += NTHR) {
            int ii = i >> 7, b = i & 127;
            g_XT[t * INF * BB + ii * BB + b] = input[(size_t)b * TT * INF + t * INF + ii];
        }
    }
    grid_bar(rel_base, barn, grp);

    const ulonglong2* ws = reinterpret_cast<const ulonglong2*>(sm + ((w < 8) ? OFS_WS0 : OFS_WS1));
    float* pbase = sm + ((w < 8) ? OFS_P0 : OFS_P1) + (w & 7) * 1024;  // [g][c][u]

    // ew role (all 512 threads, 1 scalar item each): layer el, unit eu, col ec
    const int el = tid >> 8;
    const int eu = (tid >> 7) & 1;
    const int ec = tid & 127;

    // ---- Main loop: tick tau = layer0(tau) + layer1(tau-1); one barrier/tick ----
    for (int tau = 0; tau <= TT; tau++) {
        const int pw = tau & 1;
        const int pr = pw ^ 1;

        ull acc[16];
#pragma unroll
        for (int r = 0; r < 16; r++) acc[r] = 0ull;

        bool did = false;
        if (w < 8) {
            if (tau < TT) {
                did = true;
                const int ks = w * 40, ke = ks + 40;     // 8 x 40 = K0
                if (ks < INF)   // x segment
                    gemm_seg(acc, ws, ks, min(ke, INF),
                             g_XT + tau * INF * BB, 0, lane);
                if (ke > INF)   // h0(tau-1) segment
                    gemm_seg(acc, ws, max(ks, INF), ke,
                             g_h0 + pr * HH * BB, INF, lane);
            }
        } else {
            if (tau >= 1) {
                did = true;
                const int kq = w - 8;
                const int ks = kq * 64, ke = ks + 64;    // 8 x 64 = K1
                if (kq < 4)     // h0(tau-1) half
                    gemm_seg(acc, ws, ks, ke, g_h0 + pr * HH * BB, 0, lane);
                else            // h1(tau-2) half
                    gemm_seg(acc, ws, ks, ke, g_h1 + pw * HH * BB, HH, lane);
            }
        }
        if (did) {
            // partial layout per warp: ull pp[4 g][128 c], pp[g][c] = (unit0, unit1)
            ull* pp = reinterpret_cast<ull*>(pbase);
#pragma unroll
            for (int rp = 0; rp < 4; rp++) {
                ulonglong2 v01; v01.x = acc[rp * 4 + 0]; v01.y = acc[rp * 4 + 1];
                ulonglong2 v23; v23.x = acc[rp * 4 + 2]; v23.y = acc[rp * 4 + 3];
                *reinterpret_cast<ulonglong2*>(pp + rp * 128 + 4 * lane)     = v01;
                *reinterpret_cast<ulonglong2*>(pp + rp * 128 + 4 * lane + 2) = v23;
            }
        }
        __syncthreads();

        // elementwise: each thread owns ONE (layer, unit, col) scalar
        {
            const bool doit = (el == 0) ? (tau < TT) : (tau >= 1);
            if (doit) {
                const float* pb = sm + (el ? OFS_P1 : OFS_P0);
                float gv[4];
#pragma unroll
                for (int g = 0; g < 4; g++) {
                    const int roff = g * 256 + ec * 2 + eu;   // [g][c][u]
                    float s = pb[roff];
#pragma unroll
                    for (int q = 1; q < 8; q++) s += pb[q * 1024 + roff];
                    gv[g] = s + sm[OFS_BIA + el * 8 + g * 2 + eu];
                }
                const int coff = OFS_CST + (el * 2 + eu) * 128 + ec;
                const float c_old = sm[coff];
                const float cn = sigf(gv[1]) * c_old + sigf(gv[0]) * tanhf(gv[2]);
                sm[coff] = cn;
                const float hn = sigf(gv[3]) * tanhf(cn);
                const int row = 2 * cta + eu;
                if (el == 0) {
                    __stcg(&g_h0[pw * HH * BB + row * BB + ec], hn);
                } else {
                    __stcg(&g_h1[pr * HH * BB + row * BB + ec], hn);
                    __stcg(&g_H1[(size_t)(tau - 1) * HH * BB + row * BB + ec], hn);
                }
            }
        }
        grid_bar(rel_base, barn, grp);
    }

    // ---- Deferred projection: out[b][t][o] = h1(t) . W_lin[o] + b_lin[o] ----
    for (int i = tid; i < OUTF * HH; i += NTHR) sm[i] = W_lin[i];
    if (tid < OUTF) sm[OUTF * HH + tid] = b_lin[tid];
    __syncthreads();

    // 16 warps: warp w handles timestep cta*8 + (w&7), output block (w>>3)*32..+32
    const int t = cta * 8 + (w & 7);
    const int obase = (w >> 3) * 32;
    const int bb4 = lane * 4;
    const float* hb = g_H1 + (size_t)t * HH * BB;
    for (int ob = obase; ob < obase + 32; ob += 8) {
        float acc[8][4];
#pragma unroll
        for (int oo = 0; oo < 8; oo++) { acc[oo][0] = acc[oo][1] = acc[oo][2] = acc[oo][3] = 0.f; }
        for (int j = 0; j < HH; j++) {
            const float4 hv = *reinterpret_cast<const float4*>(hb + j * BB + bb4);
#pragma unroll
            for (int oo = 0; oo < 8; oo++) {
                const float wv = sm[(ob + oo) * HH + j];
                acc[oo][0] += wv * hv.x; acc[oo][1] += wv * hv.y;
                acc[oo][2] += wv * hv.z; acc[oo][3] += wv * hv.w;
            }
        }
#pragma unroll
        for (int oo = 0; oo < 8; oo++) {
            const int o = ob + oo;
            const float bl = sm[OUTF * HH + o];
            out[(size_t)(bb4 + 0) * TT * OUTF + t * OUTF + o] = acc[oo][0] + bl;
            out[(size_t)(bb4 + 1) * TT * OUTF + t * OUTF + o] = acc[oo][1] + bl;
            out[(size_t)(bb4 + 2) * TT * OUTF + t * OUTF + o] = acc[oo][2] + bl;
            out[(size_t)(bb4 + 3) * TT * OUTF + t * OUTF + o] = acc[oo][3] + bl;
        }
    }
}

extern "C" void kernel_launch(void* const* d_in, const int* in_sizes, int n_in,
                              void* d_out, int out_size)
{
    (void)in_sizes; (void)n_in; (void)out_size;
    cudaFuncSetAttribute(lstm_persistent_kernel,
                         cudaFuncAttributeMaxDynamicSharedMemorySize, SM_BYTES);
    lstm_persistent_kernel<<<NCTA, NTHR, SM_BYTES>>>(
        (const float*)d_in[0],
        (const float*)d_in[1], (const float*)d_in[2],
        (const float*)d_in[3], (const float*)d_in[4],
        (const float*)d_in[5], (const float*)d_in[6],
        (const float*)d_in[7], (const float*)d_in[8],
        (const float*)d_in[9], (const float*)d_in[10],
        (float*)d_out);
}

// round 14
// speedup vs baseline: 1.3211x; 1.0828x over previous
#include <cuda_runtime.h>
#include <cstdint>

#define BB   128          // batch
#define TT   1024         // time steps
#define INF  64           // input features
#define HH   256          // hidden (both layers)
#define OUTF 64           // output features
#define NCTA 128
#define NTHR 512
#define K0   (INF + HH)   // 320
#define K1   (2 * HH)     // 512

typedef unsigned long long ull;

// Persistent device state (static allocs allowed; no cudaMalloc anywhere)
__device__ __align__(16) float g_XT[TT * INF * BB];   // input transposed [t][i][b]
__device__ __align__(16) float g_h0[2 * HH * BB];     // layer0 h double-buffered [p][k][b]
__device__ __align__(16) float g_h1[2 * HH * BB];     // layer1 h double-buffered
__device__ __align__(16) float g_H1[TT * HH * BB];    // all layer1 h (deferred projection)
__device__ unsigned g_arrive = 0;                     // PROVEN flat ticket-barrier counters
__device__ unsigned g_release = 0;

__device__ __forceinline__ float sigf(float x) { return 1.0f / (1.0f + __expf(-x)); }

// PROVEN flat monotonic-ticket grid barrier (byte-exact round-9 semantics).
// NOTE: the gpu-scope __threadfence here emits CCTL.IVALL -> invalidates this
// SM's L1D every tick, which is what makes the __ldca h0 loads below safe.
__device__ __forceinline__ void grid_bar(unsigned rel_base, unsigned& barn)
{
    __syncthreads();
    if (threadIdx.x == 0) {
        __threadfence();
        barn++;
        unsigned prev = atomicAdd(&g_arrive, 1u);
        if (((prev + 1u) & (NCTA - 1u)) == 0u) {
            atomicAdd(&g_release, 1u);
        } else {
            unsigned need = rel_base + barn;
            while ((int)(*(volatile unsigned*)&g_release - need) < 0) { }
        }
        __threadfence();
    }
    __syncthreads();
}

// packed dual fp32 FMA: acc(lo,hi) += a(lo,hi) * b(lo,hi)
__device__ __forceinline__ void fma2(ull& acc, ull a, ull b)
{
    asm("fma.rn.f32x2 %0, %1, %2, %0;" : "+l"(acc) : "l"(a), "l"(b));
}
// splat float into both halves of a 64-bit pair (ALU pipe)
__device__ __forceinline__ ull pk(float x)
{
    ull r; asm("mov.b64 %0, {%1, %1};" : "=l"(r) : "f"(x)); return r;
}

// GMEM-fed GEMM (proven round-9 body): row-paired FFMA2, 1-group LDG prefetch.
// CA=false: __ldcg (L2, used for x and h1 — single-read streams).
// CA=true:  __ldca (L1-cached, used for h0 — read twice per CTA per tick;
//           safe because grid_bar's gpu-scope fence flushes L1D every tick).
template <bool CA>
__device__ __forceinline__ void gemm_seg(ull* acc,
                                         const ulonglong2* __restrict__ ws,
                                         int ks, int ke,
                                         const float* __restrict__ act, int koff, int lane)
{
    const char* ap = (const char*)act + (size_t)(ks - koff) * (BB * 4) + lane * 16;
    const char* pe = (const char*)act + (size_t)(ke - koff) * (BB * 4) + lane * 16;
    float4 buf[4];
#pragma unroll
    for (int j = 0; j < 4; j++) {
        const float4* p = reinterpret_cast<const float4*>(ap + j * (BB * 4));
        buf[j] = CA ? __ldca(p) : __ldcg(p);
    }
    const char* pf = ap + 4 * (BB * 4);
    const ulonglong2* wp = ws + (size_t)ks * 2;

    for (int k = ks; k < ke; k += 4) {
#pragma unroll
        for (int j = 0; j < 4; j++) {
            const float4 a = buf[j];
            if (pf < pe) {
                const float4* p = reinterpret_cast<const float4*>(pf);
                buf[j] = CA ? __ldca(p) : __ldcg(p);
            }
            pf += BB * 4;
            const ull s0 = pk(a.x), s1 = pk(a.y), s2 = pk(a.z), s3 = pk(a.w);
            const ulonglong2 wlo = wp[0];        // row-pairs (r0,r1), (r2,r3)
            const ulonglong2 whi = wp[1];        // row-pairs (r4,r5), (r6,r7)
            wp += 2;
            fma2(acc[0],  wlo.x, s0); fma2(acc[1],  wlo.x, s1);
            fma2(acc[2],  wlo.x, s2); fma2(acc[3],  wlo.x, s3);
            fma2(acc[4],  wlo.y, s0); fma2(acc[5],  wlo.y, s1);
            fma2(acc[6],  wlo.y, s2); fma2(acc[7],  wlo.y, s3);
            fma2(acc[8],  whi.x, s0); fma2(acc[9],  whi.x, s1);
            fma2(acc[10], whi.x, s2); fma2(acc[11], whi.x, s3);
            fma2(acc[12], whi.y, s0); fma2(acc[13], whi.y, s1);
            fma2(acc[14], whi.y, s2); fma2(acc[15], whi.y, s3);
        }
    }
}

// SMEM layout (floats):
#define OFS_WS0 0                      // [K0][8]   layer0 weights (rows = gate*2+unit)
#define OFS_WS1 2560                   // [K1][8]   layer1 weights
#define OFS_P0  6656                   // [8 kq][4 g][128 c][2 u] layer0 partials
#define OFS_P1  14848                  // [8 kq][4 g][128 c][2 u] layer1 partials
#define OFS_CST 23040                  // [2 l][2 u][128 c] cell state
#define OFS_BIA 23552                  // [2 l][8 r] biases
#define SM_FLOATS 23568                // >= 16448 needed by projection phase
#define SM_BYTES  (SM_FLOATS * 4)

extern "C" __global__ void __launch_bounds__(NTHR, 1)
lstm_persistent_kernel(const float* __restrict__ input,
                       const float* __restrict__ W_ih0, const float* __restrict__ W_hh0,
                       const float* __restrict__ b_ih0, const float* __restrict__ b_hh0,
                       const float* __restrict__ W_ih1, const float* __restrict__ W_hh1,
                       const float* __restrict__ b_ih1, const float* __restrict__ b_hh1,
                       const float* __restrict__ W_lin, const float* __restrict__ b_lin,
                       float* __restrict__ out)
{
    extern __shared__ float sm[];
    const int cta  = blockIdx.x;
    const int tid  = threadIdx.x;
    const int w    = tid >> 5;         // 0..7 layer0 k-eighths, 8..15 layer1 k-eighths
    const int lane = tid & 31;

    unsigned rel_base = *(volatile unsigned*)&g_release;   // quiescent at launch start
    unsigned barn = 0;

    // ---- Phase 0: init state, stage weights, transpose input ----
    for (int i = tid; i < 512; i += NTHR) sm[OFS_CST + i] = 0.f;
    for (int i = cta * NTHR + tid; i < 2 * HH * BB; i += NCTA * NTHR) {
        g_h0[i] = 0.f;
        g_h1[i] = 0.f;
    }
    // ws0[k*8 + r] = W0[(r>>1)*HH + 2*cta + (r&1)][k], k<INF from W_ih0 else W_hh0
    for (int i = tid; i < K0 * 8; i += NTHR) {
        int k = i >> 3, r = i & 7;
        int row = (r >> 1) * HH + 2 * cta + (r & 1);
        sm[OFS_WS0 + i] = (k < INF) ? W_ih0[row * INF + k] : W_hh0[row * HH + (k - INF)];
    }
    for (int i = tid; i < K1 * 8; i += NTHR) {
        int k = i >> 3, r = i & 7;
        int row = (r >> 1) * HH + 2 * cta + (r & 1);
        sm[OFS_WS1 + i] = (k < HH) ? W_ih1[row * HH + k] : W_hh1[row * HH + (k - HH)];
    }
    if (tid < 16) {
        int l = tid >> 3, r = tid & 7;
        int row = (r >> 1) * HH + 2 * cta + (r & 1);
        sm[OFS_BIA + tid] = l ? (b_ih1[row] + b_hh1[row]) : (b_ih0[row] + b_hh0[row]);
    }
    // transpose this CTA's 8 timesteps: XT[t][i][b] = input[b][t][i]
    for (int t = cta * 8; t < cta * 8 + 8; t++) {
        for (int i = tid; i < INF * BB; i += NTHR) {
            int ii = i >> 7, b = i & 127;
            g_XT[t * INF * BB + ii * BB + b] = input[(size_t)b * TT * INF + t * INF + ii];
        }
    }
    grid_bar(rel_base, barn);

    const ulonglong2* ws = reinterpret_cast<const ulonglong2*>(sm + ((w < 8) ? OFS_WS0 : OFS_WS1));
    float* pbase = sm + ((w < 8) ? OFS_P0 : OFS_P1) + (w & 7) * 1024;  // [g][c][u]

    // ew role (all 512 threads, 1 scalar item each): layer el, unit eu, col ec
    const int el = tid >> 8;
    const int eu = (tid >> 7) & 1;
    const int ec = tid & 127;

    // ---- Main loop: tick tau = layer0(tau) + layer1(tau-1); one barrier/tick ----
    for (int tau = 0; tau <= TT; tau++) {
        const int pw = tau & 1;
        const int pr = pw ^ 1;

        ull acc[16];
#pragma unroll
        for (int r = 0; r < 16; r++) acc[r] = 0ull;

        bool did = false;
        if (w < 8) {
            if (tau < TT) {
                did = true;
                const int ks = w * 40, ke = ks + 40;     // 8 x 40 = K0
                if (ks < INF)   // x segment (stream, L2)
                    gemm_seg<false>(acc, ws, ks, min(ke, INF),
                                    g_XT + tau * INF * BB, 0, lane);
                if (ke > INF)   // h0(tau-1) segment (reused -> L1-cached)
                    gemm_seg<true>(acc, ws, max(ks, INF), ke,
                                   g_h0 + pr * HH * BB, INF, lane);
            }
        } else {
            if (tau >= 1) {
                did = true;
                const int kq = w - 8;
                const int ks = kq * 64, ke = ks + 64;    // 8 x 64 = K1
                if (kq < 4)     // h0(tau-1) half (reused -> L1-cached)
                    gemm_seg<true>(acc, ws, ks, ke, g_h0 + pr * HH * BB, 0, lane);
                else            // h1(tau-2) half (stream, L2)
                    gemm_seg<false>(acc, ws, ks, ke, g_h1 + pw * HH * BB, HH, lane);
            }
        }
        if (did) {
            // partial layout per warp: ull pp[4 g][128 c], pp[g][c] = (unit0, unit1)
            ull* pp = reinterpret_cast<ull*>(pbase);
#pragma unroll
            for (int rp = 0; rp < 4; rp++) {
                ulonglong2 v01; v01.x = acc[rp * 4 + 0]; v01.y = acc[rp * 4 + 1];
                ulonglong2 v23; v23.x = acc[rp * 4 + 2]; v23.y = acc[rp * 4 + 3];
                *reinterpret_cast<ulonglong2*>(pp + rp * 128 + 4 * lane)     = v01;
                *reinterpret_cast<ulonglong2*>(pp + rp * 128 + 4 * lane + 2) = v23;
            }
        }
        __syncthreads();

        // elementwise: each thread owns ONE (layer, unit, col) scalar
        {
            const bool doit = (el == 0) ? (tau < TT) : (tau >= 1);
            if (doit) {
                const float* pb = sm + (el ? OFS_P1 : OFS_P0);
                float gv[4];
#pragma unroll
                for (int g = 0; g < 4; g++) {
                    const int roff = g * 256 + ec * 2 + eu;   // [g][c][u]
                    float s = pb[roff];
#pragma unroll
                    for (int q = 1; q < 8; q++) s += pb[q * 1024 + roff];
                    gv[g] = s + sm[OFS_BIA + el * 8 + g * 2 + eu];
                }
                const int coff = OFS_CST + (el * 2 + eu) * 128 + ec;
                const float c_old = sm[coff];
                const float cn = sigf(gv[1]) * c_old + sigf(gv[0]) * tanhf(gv[2]);
                sm[coff] = cn;
                const float hn = sigf(gv[3]) * tanhf(cn);
                const int row = 2 * cta + eu;
                if (el == 0) {
                    __stcg(&g_h0[pw * HH * BB + row * BB + ec], hn);
                } else {
                    __stcg(&g_h1[pr * HH * BB + row * BB + ec], hn);
                    __stcg(&g_H1[(size_t)(tau - 1) * HH * BB + row * BB + ec], hn);
                }
            }
        }
        grid_bar(rel_base, barn);
    }

    // ---- Deferred projection: out[b][t][o] = h1(t) . W_lin[o] + b_lin[o] ----
    for (int i = tid; i < OUTF * HH; i += NTHR) sm[i] = W_lin[i];
    if (tid < OUTF) sm[OUTF * HH + tid] = b_lin[tid];
    __syncthreads();

    // 16 warps: warp w handles timestep cta*8 + (w&7), output block (w>>3)*32..+32
    const int t = cta * 8 + (w & 7);
    const int obase = (w >> 3) * 32;
    const int bb4 = lane * 4;
    const float* hb = g_H1 + (size_t)t * HH * BB;
    for (int ob = obase; ob < obase + 32; ob += 8) {
        float acc[8][4];
#pragma unroll
        for (int oo = 0; oo < 8; oo++) { acc[oo][0] = acc[oo][1] = acc[oo][2] = acc[oo][3] = 0.f; }
        for (int j = 0; j < HH; j++) {
            const float4 hv = *reinterpret_cast<const float4*>(hb + j * BB + bb4);
#pragma unroll
            for (int oo = 0; oo < 8; oo++) {
                const float wv = sm[(ob + oo) * HH + j];
                acc[oo][0] += wv * hv.x; acc[oo][1] += wv * hv.y;
                acc[oo][2] += wv * hv.z; acc[oo][3] += wv * hv.w;
            }
        }
#pragma unroll
        for (int oo = 0; oo < 8; oo++) {
            const int o = ob + oo;
            const float bl = sm[OUTF * HH + o];
            out[(size_t)(bb4 + 0) * TT * OUTF + t * OUTF + o] = acc[oo][0] + bl;
            out[(size_t)(bb4 + 1) * TT * OUTF + t * OUTF + o] = acc[oo][1] + bl;
            out[(size_t)(bb4 + 2) * TT * OUTF + t * OUTF + o] = acc[oo][2] + bl;
            out[(size_t)(bb4 + 3) * TT * OUTF + t * OUTF + o] = acc[oo][3] + bl;
        }
    }
}

extern "C" void kernel_launch(void* const* d_in, const int* in_sizes, int n_in,
                              void* d_out, int out_size)
{
    (void)in_sizes; (void)n_in; (void)out_size;
    cudaFuncSetAttribute(lstm_persistent_kernel,
                         cudaFuncAttributeMaxDynamicSharedMemorySize, SM_BYTES);
    lstm_persistent_kernel<<<NCTA, NTHR, SM_BYTES>>>(
        (const float*)d_in[0],
        (const float*)d_in[1], (const float*)d_in[2],
        (const float*)d_in[3], (const float*)d_in[4],
        (const float*)d_in[5], (const float*)d_in[6],
        (const float*)d_in[7], (const float*)d_in[8],
        (const float*)d_in[9], (const float*)d_in[10],
        (float*)d_out);
}

// round 15
// speedup vs baseline: 1.3456x; 1.0186x over previous
#include <cuda_runtime.h>
#include <cstdint>

#define BB   128          // batch
#define TT   1024         // time steps
#define INF  64           // input features
#define HH   256          // hidden (both layers)
#define OUTF 64           // output features
#define NCTA 128
#define NTHR 512
#define K0   (INF + HH)   // 320
#define K1   (2 * HH)     // 512

typedef unsigned long long ull;

// Persistent device state (static allocs allowed; no cudaMalloc anywhere)
__device__ __align__(16) float g_XT[TT * INF * BB];   // input transposed [t][i][b]
__device__ __align__(16) float g_h0[2 * HH * BB];     // layer0 h double-buffered [p][k][b]
__device__ __align__(16) float g_h1[2 * HH * BB];     // layer1 h double-buffered
__device__ __align__(16) float g_H1[TT * HH * BB];    // all layer1 h (deferred projection)
__device__ unsigned g_arrive = 0;                     // single barrier counter (reset per launch)

__device__ __forceinline__ float sigf(float x) { return 1.0f / (1.0f + __expf(-x)); }

// Round-15 barrier: reset-prelude zeroes g_arrive each launch, so target is
// simply barn*NCTA. Arrival is red.global.add (fire-and-forget -> no 318cyc
// atomic return on the critical path, no release hop); everyone polls the
// counter with the PROVEN volatile-load form. Deadlock-free by construction:
// one monotonic counter, increment-then-wait-for-global-count.
__device__ __forceinline__ void grid_bar(unsigned& barn)
{
    __syncthreads();
    if (threadIdx.x == 0) {
        __threadfence();
        barn++;
        asm volatile("red.global.add.u32 [%0], 1;" :: "l"(&g_arrive) : "memory");
        const unsigned need = barn * (unsigned)NCTA;
        while ((int)(*(volatile unsigned*)&g_arrive - need) < 0) { }
        __threadfence();
    }
    __syncthreads();
}

// packed dual fp32 FMA: acc(lo,hi) += a(lo,hi) * b(lo,hi)
__device__ __forceinline__ void fma2(ull& acc, ull a, ull b)
{
    asm("fma.rn.f32x2 %0, %1, %2, %0;" : "+l"(acc) : "l"(a), "l"(b));
}
// splat float into both halves of a 64-bit pair (ALU pipe)
__device__ __forceinline__ ull pk(float x)
{
    ull r; asm("mov.b64 %0, {%1, %1};" : "=l"(r) : "f"(x)); return r;
}

// GMEM-fed GEMM (proven round-9/14 body): row-paired FFMA2, 1-group LDG prefetch.
// CA=false: __ldcg (L2, x and h1 — single-read streams).
// CA=true:  __ldca (L1-cached, h0 — read twice per CTA per tick; safe because
//           grid_bar's gpu-scope fence flushes L1D every tick).
template <bool CA>
__device__ __forceinline__ void gemm_seg(ull* acc,
                                         const ulonglong2* __restrict__ ws,
                                         int ks, int ke,
                                         const float* __restrict__ act, int koff, int lane)
{
    const char* ap = (const char*)act + (size_t)(ks - koff) * (BB * 4) + lane * 16;
    const char* pe = (const char*)act + (size_t)(ke - koff) * (BB * 4) + lane * 16;
    float4 buf[4];
#pragma unroll
    for (int j = 0; j < 4; j++) {
        const float4* p = reinterpret_cast<const float4*>(ap + j * (BB * 4));
        buf[j] = CA ? __ldca(p) : __ldcg(p);
    }
    const char* pf = ap + 4 * (BB * 4);
    const ulonglong2* wp = ws + (size_t)ks * 2;

    for (int k = ks; k < ke; k += 4) {
#pragma unroll
        for (int j = 0; j < 4; j++) {
            const float4 a = buf[j];
            if (pf < pe) {
                const float4* p = reinterpret_cast<const float4*>(pf);
                buf[j] = CA ? __ldca(p) : __ldcg(p);
            }
            pf += BB * 4;
            const ull s0 = pk(a.x), s1 = pk(a.y), s2 = pk(a.z), s3 = pk(a.w);
            const ulonglong2 wlo = wp[0];        // row-pairs (r0,r1), (r2,r3)
            const ulonglong2 whi = wp[1];        // row-pairs (r4,r5), (r6,r7)
            wp += 2;
            fma2(acc[0],  wlo.x, s0); fma2(acc[1],  wlo.x, s1);
            fma2(acc[2],  wlo.x, s2); fma2(acc[3],  wlo.x, s3);
            fma2(acc[4],  wlo.y, s0); fma2(acc[5],  wlo.y, s1);
            fma2(acc[6],  wlo.y, s2); fma2(acc[7],  wlo.y, s3);
            fma2(acc[8],  whi.x, s0); fma2(acc[9],  whi.x, s1);
            fma2(acc[10], whi.x, s2); fma2(acc[11], whi.x, s3);
            fma2(acc[12], whi.y, s0); fma2(acc[13], whi.y, s1);
            fma2(acc[14], whi.y, s2); fma2(acc[15], whi.y, s3);
        }
    }
}

// SMEM layout (floats):
#define OFS_WS0 0                      // [K0][8]   layer0 weights (rows = gate*2+unit)
#define OFS_WS1 2560                   // [K1][8]   layer1 weights
#define OFS_P0  6656                   // [8 kq][4 g][128 c][2 u] layer0 partials
#define OFS_P1  14848                  // [8 kq][4 g][128 c][2 u] layer1 partials
#define OFS_CST 23040                  // [2 l][2 u][128 c] cell state
#define OFS_BIA 23552                  // [2 l][8 r] biases
#define SM_FLOATS 23568                // >= 16448 needed by projection phase
#define SM_BYTES  (SM_FLOATS * 4)

// Reset prelude: zero the barrier counter before each main-kernel run.
// Stream-ordered ahead of the main kernel inside the captured graph.
extern "C" __global__ void barrier_reset_kernel()
{
    g_arrive = 0;
}

extern "C" __global__ void __launch_bounds__(NTHR, 1)
lstm_persistent_kernel(const float* __restrict__ input,
                       const float* __restrict__ W_ih0, const float* __restrict__ W_hh0,
                       const float* __restrict__ b_ih0, const float* __restrict__ b_hh0,
                       const float* __restrict__ W_ih1, const float* __restrict__ W_hh1,
                       const float* __restrict__ b_ih1, const float* __restrict__ b_hh1,
                       const float* __restrict__ W_lin, const float* __restrict__ b_lin,
                       float* __restrict__ out)
{
    extern __shared__ float sm[];
    const int cta  = blockIdx.x;
    const int tid  = threadIdx.x;
    const int w    = tid >> 5;         // 0..7 layer0 k-eighths, 8..15 layer1 k-eighths
    const int lane = tid & 31;

    unsigned barn = 0;

    // ---- Phase 0: init state, stage weights, transpose input ----
    for (int i = tid; i < 512; i += NTHR) sm[OFS_CST + i] = 0.f;
    for (int i = cta * NTHR + tid; i < 2 * HH * BB; i += NCTA * NTHR) {
        g_h0[i] = 0.f;
        g_h1[i] = 0.f;
    }
    // ws0[k*8 + r] = W0[(r>>1)*HH + 2*cta + (r&1)][k], k<INF from W_ih0 else W_hh0
    for (int i = tid; i < K0 * 8; i += NTHR) {
        int k = i >> 3, r = i & 7;
        int row = (r >> 1) * HH + 2 * cta + (r & 1);
        sm[OFS_WS0 + i] = (k < INF) ? W_ih0[row * INF + k] : W_hh0[row * HH + (k - INF)];
    }
    for (int i = tid; i < K1 * 8; i += NTHR) {
        int k = i >> 3, r = i & 7;
        int row = (r >> 1) * HH + 2 * cta + (r & 1);
        sm[OFS_WS1 + i] = (k < HH) ? W_ih1[row * HH + k] : W_hh1[row * HH + (k - HH)];
    }
    if (tid < 16) {
        int l = tid >> 3, r = tid & 7;
        int row = (r >> 1) * HH + 2 * cta + (r & 1);
        sm[OFS_BIA + tid] = l ? (b_ih1[row] + b_hh1[row]) : (b_ih0[row] + b_hh0[row]);
    }
    // transpose this CTA's 8 timesteps: XT[t][i][b] = input[b][t][i]
    for (int t = cta * 8; t < cta * 8 + 8; t++) {
        for (int i = tid; i < INF * BB; i += NTHR) {
            int ii = i >> 7, b = i & 127;
            g_XT[t * INF * BB + ii * BB + b] = input[(size_t)b * TT * INF + t * INF + ii];
        }
    }
    grid_bar(barn);

    const ulonglong2* ws = reinterpret_cast<const ulonglong2*>(sm + ((w < 8) ? OFS_WS0 : OFS_WS1));
    float* pbase = sm + ((w < 8) ? OFS_P0 : OFS_P1) + (w & 7) * 1024;  // [g][c][u]

    // ew role (all 512 threads, 1 scalar item each): layer el, unit eu, col ec
    const int el = tid >> 8;
    const int eu = (tid >> 7) & 1;
    const int ec = tid & 127;

    // ---- Main loop: tick tau = layer0(tau) + layer1(tau-1); one barrier/tick ----
    for (int tau = 0; tau <= TT; tau++) {
        const int pw = tau & 1;
        const int pr = pw ^ 1;

        ull acc[16];
#pragma unroll
        for (int r = 0; r < 16; r++) acc[r] = 0ull;

        bool did = false;
        if (w < 8) {
            if (tau < TT) {
                did = true;
                const int ks = w * 40, ke = ks + 40;     // 8 x 40 = K0
                if (ks < INF)   // x segment (stream, L2)
                    gemm_seg<false>(acc, ws, ks, min(ke, INF),
                                    g_XT + tau * INF * BB, 0, lane);
                if (ke > INF)   // h0(tau-1) segment (reused -> L1-cached)
                    gemm_seg<true>(acc, ws, max(ks, INF), ke,
                                   g_h0 + pr * HH * BB, INF, lane);
            }
        } else {
            if (tau >= 1) {
                did = true;
                const int kq = w - 8;
                const int ks = kq * 64, ke = ks + 64;    // 8 x 64 = K1
                if (kq < 4)     // h0(tau-1) half (reused -> L1-cached)
                    gemm_seg<true>(acc, ws, ks, ke, g_h0 + pr * HH * BB, 0, lane);
                else            // h1(tau-2) half (stream, L2)
                    gemm_seg<false>(acc, ws, ks, ke, g_h1 + pw * HH * BB, HH, lane);
            }
        }
        if (did) {
            // partial layout per warp: ull pp[4 g][128 c], pp[g][c] = (unit0, unit1)
            ull* pp = reinterpret_cast<ull*>(pbase);
#pragma unroll
            for (int rp = 0; rp < 4; rp++) {
                ulonglong2 v01; v01.x = acc[rp * 4 + 0]; v01.y = acc[rp * 4 + 1];
                ulonglong2 v23; v23.x = acc[rp * 4 + 2]; v23.y = acc[rp * 4 + 3];
                *reinterpret_cast<ulonglong2*>(pp + rp * 128 + 4 * lane)     = v01;
                *reinterpret_cast<ulonglong2*>(pp + rp * 128 + 4 * lane + 2) = v23;
            }
        }
        __syncthreads();

        // elementwise: each thread owns ONE (layer, unit, col) scalar
        {
            const bool doit = (el == 0) ? (tau < TT) : (tau >= 1);
            if (doit) {
                const float* pb = sm + (el ? OFS_P1 : OFS_P0);
                float gv[4];
#pragma unroll
                for (int g = 0; g < 4; g++) {
                    const int roff = g * 256 + ec * 2 + eu;   // [g][c][u]
                    float s = pb[roff];
#pragma unroll
                    for (int q = 1; q < 8; q++) s += pb[q * 1024 + roff];
                    gv[g] = s + sm[OFS_BIA + el * 8 + g * 2 + eu];
                }
                const int coff = OFS_CST + (el * 2 + eu) * 128 + ec;
                const float c_old = sm[coff];
                const float cn = sigf(gv[1]) * c_old + sigf(gv[0]) * tanhf(gv[2]);
                sm[coff] = cn;
                const float hn = sigf(gv[3]) * tanhf(cn);
                const int row = 2 * cta + eu;
                if (el == 0) {
                    __stcg(&g_h0[pw * HH * BB + row * BB + ec], hn);
                } else {
                    __stcg(&g_h1[pr * HH * BB + row * BB + ec], hn);
                    __stcg(&g_H1[(size_t)(tau - 1) * HH * BB + row * BB + ec], hn);
                }
            }
        }
        grid_bar(barn);
    }

    // ---- Deferred projection: out[b][t][o] = h1(t) . W_lin[o] + b_lin[o] ----
    for (int i = tid; i < OUTF * HH; i += NTHR) sm[i] = W_lin[i];
    if (tid < OUTF) sm[OUTF * HH + tid] = b_lin[tid];
    __syncthreads();

    // 16 warps: warp w handles timestep cta*8 + (w&7), output block (w>>3)*32..+32
    const int t = cta * 8 + (w & 7);
    const int obase = (w >> 3) * 32;
    const int bb4 = lane * 4;
    const float* hb = g_H1 + (size_t)t * HH * BB;
    for (int ob = obase; ob < obase + 32; ob += 8) {
        float acc[8][4];
#pragma unroll
        for (int oo = 0; oo < 8; oo++) { acc[oo][0] = acc[oo][1] = acc[oo][2] = acc[oo][3] = 0.f; }
        for (int j = 0; j < HH; j++) {
            const float4 hv = *reinterpret_cast<const float4*>(hb + j * BB + bb4);
#pragma unroll
            for (int oo = 0; oo < 8; oo++) {
                const float wv = sm[(ob + oo) * HH + j];
                acc[oo][0] += wv * hv.x; acc[oo][1] += wv * hv.y;
                acc[oo][2] += wv * hv.z; acc[oo][3] += wv * hv.w;
            }
        }
#pragma unroll
        for (int oo = 0; oo < 8; oo++) {
            const int o = ob + oo;
            const float bl = sm[OUTF * HH + o];
            out[(size_t)(bb4 + 0) * TT * OUTF + t * OUTF + o] = acc[oo][0] + bl;
            out[(size_t)(bb4 + 1) * TT * OUTF + t * OUTF + o] = acc[oo][1] + bl;
            out[(size_t)(bb4 + 2) * TT * OUTF + t * OUTF + o] = acc[oo][2] + bl;
            out[(size_t)(bb4 + 3) * TT * OUTF + t * OUTF + o] = acc[oo][3] + bl;
        }
    }
}

extern "C" void kernel_launch(void* const* d_in, const int* in_sizes, int n_in,
                              void* d_out, int out_size)
{
    (void)in_sizes; (void)n_in; (void)out_size;
    cudaFuncSetAttribute(lstm_persistent_kernel,
                         cudaFuncAttributeMaxDynamicSharedMemorySize, SM_BYTES);
    barrier_reset_kernel<<<1, 1>>>();
    lstm_persistent_kernel<<<NCTA, NTHR, SM_BYTES>>>(
        (const float*)d_in[0],
        (const float*)d_in[1], (const float*)d_in[2],
        (const float*)d_in[3], (const float*)d_in[4],
        (const float*)d_in[5], (const float*)d_in[6],
        (const float*)d_in[7], (const float*)d_in[8],
        (const float*)d_in[9], (const float*)d_in[10],
        (float*)d_out);
}